// round 11
// baseline (speedup 1.0000x reference)
#include <cuda_runtime.h>
#include <cuda_bf16.h>
#include <cstdint>

// GATv2 fused: B=8,T=32,N=64,F=64,U=64,H=4 (BT=256), one CTA/graph.
// Proj + agg on mma.sync.m16n8k16.bf16 (3-term split, fp32 acc).
// Pairwise+softmax fused in registers (no score buffer); p/q+SBF from smem.

#define XLD 144
#define WLD 272
#define LDs 68
#define OFF_AX 0
#define OFF_BW 18432
#define OFF_ATT 18432            // overlay (post-proj)
#define OFF_SBF (18432 + 17408)  // overlay (post-proj)
#define OFF_SF 53248
#define OFF_DT 70656
#define OFF_AS 88064
#define OFF_A8 88320
#define OFF_PS 88576
#define OFF_QS 88832
#define OFF_ADJ 89088
#define SMEM_TOTAL 89600
#define BLOBSZ 34816

__device__ __align__(256) unsigned char g_wblob[4 * BLOBSZ];

__device__ __forceinline__ uint32_t smem_u32(const void* p) {
    uint32_t a;
    asm("{ .reg .u64 t; cvta.to.shared.u64 t, %1; cvt.u32.u64 %0, t; }" : "=r"(a) : "l"(p));
    return a;
}
__device__ __forceinline__ void ldsm4(uint32_t* r, uint32_t a) {
    asm volatile("ldmatrix.sync.aligned.m8n8.x4.shared.b16 {%0,%1,%2,%3}, [%4];"
        : "=r"(r[0]), "=r"(r[1]), "=r"(r[2]), "=r"(r[3]) : "r"(a));
}
__device__ __forceinline__ void ldsm4t(uint32_t* r, uint32_t a) {
    asm volatile("ldmatrix.sync.aligned.m8n8.x4.trans.shared.b16 {%0,%1,%2,%3}, [%4];"
        : "=r"(r[0]), "=r"(r[1]), "=r"(r[2]), "=r"(r[3]) : "r"(a));
}
__device__ __forceinline__ void hmma(float* c, const uint32_t* a, uint32_t b0, uint32_t b1) {
    asm volatile("mma.sync.aligned.m16n8k16.row.col.f32.bf16.bf16.f32 "
        "{%0,%1,%2,%3}, {%4,%5,%6,%7}, {%8,%9}, {%0,%1,%2,%3};"
        : "+f"(c[0]), "+f"(c[1]), "+f"(c[2]), "+f"(c[3])
        : "r"(a[0]), "r"(a[1]), "r"(a[2]), "r"(a[3]), "r"(b0), "r"(b1));
}
__device__ __forceinline__ unsigned long long pack2(float lo, float hi) {
    unsigned long long r; asm("mov.b64 %0, {%1,%2};" : "=l"(r) : "f"(lo), "f"(hi)); return r;
}
__device__ __forceinline__ void unpack2(unsigned long long v, float& lo, float& hi) {
    asm("mov.b64 {%0,%1}, %2;" : "=f"(lo), "=f"(hi) : "l"(v));
}
__device__ __forceinline__ unsigned long long add2(unsigned long long a, unsigned long long b) {
    unsigned long long r; asm("add.rn.f32x2 %0, %1, %2;" : "=l"(r) : "l"(a), "l"(b)); return r;
}
__device__ __forceinline__ unsigned long long fma2(unsigned long long a, unsigned long long b, unsigned long long c) {
    unsigned long long r; asm("fma.rn.f32x2 %0, %1, %2, %3;" : "=l"(r) : "l"(a), "l"(b), "l"(c)); return r;
}
__device__ __forceinline__ unsigned long long relu2(unsigned long long v) {
    float lo, hi; unpack2(v, lo, hi); lo = fmaxf(lo, 0.f); hi = fmaxf(hi, 0.f); return pack2(lo, hi);
}
__device__ __forceinline__ float f4get(const float4& v, int i) {
    switch (i & 3) { case 0: return v.x; case 1: return v.y; case 2: return v.z; default: return v.w; }
}
__device__ __forceinline__ void split2(float v0, float v1, uint32_t& hw, uint32_t& lw) {
    __nv_bfloat16 h0 = __float2bfloat16(v0), h1 = __float2bfloat16(v1);
    hw = ((uint32_t)__bfloat16_as_ushort(h1) << 16) | __bfloat16_as_ushort(h0);
    __nv_bfloat16 l0 = __float2bfloat16(v0 - __bfloat162float(h0));
    __nv_bfloat16 l1 = __float2bfloat16(v1 - __bfloat162float(h1));
    lw = ((uint32_t)__bfloat16_as_ushort(l1) << 16) | __bfloat16_as_ushort(l0);
}

__global__ void prep_w(const float* __restrict__ Ws, const float* __restrict__ Wd) {
    int h = blockIdx.x;
    unsigned char* base = g_wblob + h * BLOBSZ;
    for (int idx = threadIdx.x; idx < 64 * 128; idx += 256) {
        int k = idx >> 7, n = idx & 127;
        float w = (n < 64) ? Ws[h * 4096 + k * 64 + n] : Wd[h * 4096 + k * 64 + (n - 64)];
        __nv_bfloat16 hi = __float2bfloat16(w);
        __nv_bfloat16 lo = __float2bfloat16(w - __bfloat162float(hi));
        int byt = (k * 136 + n) * 2;
        *(unsigned short*)(base + byt)         = __bfloat16_as_ushort(hi);
        *(unsigned short*)(base + 17408 + byt) = __bfloat16_as_ushort(lo);
    }
}

__global__ void __launch_bounds__(256, 2) gat_mma_kernel(
    const float* __restrict__ feat, const int* __restrict__ adj,
    const float* __restrict__ avec, float* __restrict__ outp)
{
    extern __shared__ char smem[];
    const uint32_t sb = smem_u32(smem);   // shared-space: ONLY for ldmatrix/mma asm
    float* Sf = (float*)(smem + OFF_SF);
    float* Dt = (float*)(smem + OFF_DT);
    float* aS = (float*)(smem + OFF_AS);
    float* a8 = (float*)(smem + OFF_A8);
    float* ps = (float*)(smem + OFF_PS);
    float* qs = (float*)(smem + OFF_QS);
    unsigned long long* adjb = (unsigned long long*)(smem + OFF_ADJ);

    const int tid = threadIdx.x, wid = tid >> 5, lid = tid & 31;
    const int bt = blockIdx.x, b = bt >> 5;
    const int mr = lid >> 2, nc = (lid & 3) << 1;
    const int ib = (wid & 3) << 4;
    const int nh = wid >> 2;

    // ---- stage X split + adjacency ----
    {
        const float4* xp = (const float4*)(feat + bt * 4096);
        for (int idx = tid; idx < 1024; idx += 256) {
            float4 v = xp[idx];
            int i = idx >> 4, f0 = (idx & 15) << 2;
            uint32_t h01, l01, h23, l23;
            split2(v.x, v.y, h01, l01);
            split2(v.z, v.w, h23, l23);
            *(uint2*)(smem + OFF_AX + i * XLD + f0 * 2)        = make_uint2(h01, h23);
            *(uint2*)(smem + OFF_AX + (64 + i) * XLD + f0 * 2) = make_uint2(l01, l23);
        }
        if (tid < 64) {
            const int* ar = adj + b * 4096 + tid * 64;
            unsigned long long m = 1ull << tid;
            #pragma unroll 8
            for (int j = 0; j < 64; j++) if (ar[j] > 0) m |= (1ull << j);
            adjb[tid] = m;
        }
    }

    float cacc[4][4];
    #pragma unroll
    for (int t = 0; t < 4; t++) { cacc[t][0] = cacc[t][1] = cacc[t][2] = cacc[t][3] = 0.f; }

    for (int h = 0; h < 4; h++) {
        {   // ---- stage W blob + a ----
            const float4* src = (const float4*)(g_wblob + h * BLOBSZ);
            float4* dst = (float4*)(smem + OFF_BW);
            for (int k = tid; k < BLOBSZ / 16; k += 256) dst[k] = src[k];
            if (tid < 64) {
                float av = avec[h * 64 + tid];
                aS[tid] = av; a8[tid] = 0.8f * av;
            }
        }
        __syncthreads();

        // ---- projection (3-pass); pacc dies at end of this block ----
        {
            uint32_t ahi[4][4], alo[4][4];
            uint32_t abase = sb + OFF_AX + (ib + (lid & 15)) * XLD + ((lid >> 4) << 4);
            #pragma unroll
            for (int kc = 0; kc < 4; kc++) {
                ldsm4(ahi[kc], abase + kc * 32);
                ldsm4(alo[kc], abase + 64 * XLD + kc * 32);
            }
            float pacc[8][4];
            #pragma unroll
            for (int t = 0; t < 8; t++) { pacc[t][0] = pacc[t][1] = pacc[t][2] = pacc[t][3] = 0.f; }
            #pragma unroll
            for (int pass = 0; pass < 3; pass++) {
                const int wofs = (pass == 2) ? 17408 : 0;
                #pragma unroll
                for (int kc = 0; kc < 4; kc++) {
                    const uint32_t* af = (pass == 1) ? alo[kc] : ahi[kc];
                    uint32_t wb = sb + OFF_BW + wofs + ((kc << 4) + (lid & 15)) * WLD
                                + nh * 128 + ((lid >> 4) << 4);
                    #pragma unroll
                    for (int np = 0; np < 4; np++) {
                        uint32_t bf[4];
                        ldsm4t(bf, wb + np * 32);
                        hmma(pacc[2 * np],     af, bf[0], bf[1]);
                        hmma(pacc[2 * np + 1], af, bf[2], bf[3]);
                    }
                }
            }
            if (nh == 0) {
                #pragma unroll
                for (int nt = 0; nt < 8; nt++) {
                    int u = (nt << 3) + nc;
                    *(float2*)&Sf[(ib + mr) * LDs + u]     = make_float2(pacc[nt][0], pacc[nt][1]);
                    *(float2*)&Sf[(ib + mr + 8) * LDs + u] = make_float2(pacc[nt][2], pacc[nt][3]);
                }
            } else {
                #pragma unroll
                for (int nt = 0; nt < 8; nt++) {
                    int u = (nt << 3) + nc;
                    Dt[u * LDs + ib + mr]           = pacc[nt][0];
                    Dt[(u + 1) * LDs + ib + mr]     = pacc[nt][1];
                    Dt[u * LDs + ib + mr + 8]       = pacc[nt][2];
                    Dt[(u + 1) * LDs + ib + mr + 8] = pacc[nt][3];
                }
            }
        }
        __syncthreads();

        // ---- p/q (all threads, from smem) + emit S bf16 split (SBF) ----
        {
            int j = tid >> 2, qd = tid & 3, ug = qd << 4;
            float pv = 0.f, qv = 0.f;
            unsigned char* sb_row = (unsigned char*)smem + OFF_SBF + j * WLD;
            #pragma unroll
            for (int c4 = 0; c4 < 16; c4 += 4) {
                float4 sv = *(const float4*)&Sf[j * LDs + ug + c4];
                float4 av = *(const float4*)&aS[ug + c4];
                pv += av.x * sv.x + av.y * sv.y + av.z * sv.z + av.w * sv.w;
                uint32_t hw0, lw0, hw1, lw1;
                split2(sv.x, sv.y, hw0, lw0);
                split2(sv.z, sv.w, hw1, lw1);
                *(uint32_t*)(sb_row + (ug + c4) * 2)           = hw0;
                *(uint32_t*)(sb_row + (ug + c4 + 2) * 2)       = hw1;
                *(uint32_t*)(sb_row + 128 + (ug + c4) * 2)     = lw0;
                *(uint32_t*)(sb_row + 128 + (ug + c4 + 2) * 2) = lw1;
            }
            #pragma unroll
            for (int c = 0; c < 16; c++)
                qv += aS[ug + c] * Dt[(ug + c) * LDs + j];
            pv += __shfl_xor_sync(~0u, pv, 1); pv += __shfl_xor_sync(~0u, pv, 2);
            qv += __shfl_xor_sync(~0u, qv, 1); qv += __shfl_xor_sync(~0u, qv, 2);
            if (qd == 0) { ps[j] = pv; qs[j] = qv; }
        }
        __syncthreads();

        // ---- pairwise + softmax fused (2 rows x 8 cols per thread) ----
        {
            const int ihalf = lid >> 3, g = lid & 7;
            const int i0 = (wid << 2) + ihalf, i1 = i0 + 32, j0 = g << 3;
            unsigned long long acA[4], acB[4];
            #pragma unroll
            for (int t = 0; t < 4; t++) { acA[t] = 0ull; acB[t] = 0ull; }
            #pragma unroll 2
            for (int u4 = 0; u4 < 64; u4 += 4) {
                float4 sa = *(const float4*)&Sf[i0 * LDs + u4];
                float4 sbv = *(const float4*)&Sf[i1 * LDs + u4];
                float4 a84 = *(const float4*)&a8[u4];
                #pragma unroll
                for (int uu = 0; uu < 4; uu++) {
                    ulonglong2 d0 = *(const ulonglong2*)&Dt[(u4 + uu) * LDs + j0];
                    ulonglong2 d1 = *(const ulonglong2*)&Dt[(u4 + uu) * LDs + j0 + 4];
                    float a8u = f4get(a84, uu);
                    unsigned long long a2 = pack2(a8u, a8u);
                    float s_ = f4get(sa, uu);
                    unsigned long long s2 = pack2(s_, s_);
                    acA[0] = fma2(a2, relu2(add2(s2, d0.x)), acA[0]);
                    acA[1] = fma2(a2, relu2(add2(s2, d0.y)), acA[1]);
                    acA[2] = fma2(a2, relu2(add2(s2, d1.x)), acA[2]);
                    acA[3] = fma2(a2, relu2(add2(s2, d1.y)), acA[3]);
                    s_ = f4get(sbv, uu);
                    s2 = pack2(s_, s_);
                    acB[0] = fma2(a2, relu2(add2(s2, d0.x)), acB[0]);
                    acB[1] = fma2(a2, relu2(add2(s2, d0.y)), acB[1]);
                    acB[2] = fma2(a2, relu2(add2(s2, d1.x)), acB[2]);
                    acB[3] = fma2(a2, relu2(add2(s2, d1.y)), acB[3]);
                }
            }
            float qv[8];
            {
                float4 t0 = *(const float4*)&qs[j0];
                float4 t1 = *(const float4*)&qs[j0 + 4];
                qv[0]=t0.x; qv[1]=t0.y; qv[2]=t0.z; qv[3]=t0.w;
                qv[4]=t1.x; qv[5]=t1.y; qv[6]=t1.z; qv[7]=t1.w;
            }
            float pi0 = ps[i0], pi1 = ps[i1];
            float vA[8], vB[8];
            unpack2(acA[0], vA[0], vA[1]); unpack2(acA[1], vA[2], vA[3]);
            unpack2(acA[2], vA[4], vA[5]); unpack2(acA[3], vA[6], vA[7]);
            unpack2(acB[0], vB[0], vB[1]); unpack2(acB[1], vB[2], vB[3]);
            unpack2(acB[2], vB[4], vB[5]); unpack2(acB[3], vB[6], vB[7]);
            unsigned mA = (unsigned)(adjb[i0] >> j0) & 0xFFu;
            unsigned mB = (unsigned)(adjb[i1] >> j0) & 0xFFu;
            float mxA = -3.0e38f, mxB = -3.0e38f;
            #pragma unroll
            for (int c = 0; c < 8; c++) {
                vA[c] = ((mA >> c) & 1u) ? (0.2f * (pi0 + qv[c]) + vA[c]) : -1e9f;
                vB[c] = ((mB >> c) & 1u) ? (0.2f * (pi1 + qv[c]) + vB[c]) : -1e9f;
                mxA = fmaxf(mxA, vA[c]); mxB = fmaxf(mxB, vB[c]);
            }
            mxA = fmaxf(mxA, __shfl_xor_sync(~0u, mxA, 1));
            mxA = fmaxf(mxA, __shfl_xor_sync(~0u, mxA, 2));
            mxA = fmaxf(mxA, __shfl_xor_sync(~0u, mxA, 4));
            mxB = fmaxf(mxB, __shfl_xor_sync(~0u, mxB, 1));
            mxB = fmaxf(mxB, __shfl_xor_sync(~0u, mxB, 2));
            mxB = fmaxf(mxB, __shfl_xor_sync(~0u, mxB, 4));
            float sA = 0.f, sB = 0.f;
            #pragma unroll
            for (int c = 0; c < 8; c++) {
                vA[c] = exp2f((vA[c] - mxA) * 1.4426950408889634f);
                vB[c] = exp2f((vB[c] - mxB) * 1.4426950408889634f);
                sA += vA[c]; sB += vB[c];
            }
            sA += __shfl_xor_sync(~0u, sA, 1); sA += __shfl_xor_sync(~0u, sA, 2);
            sA += __shfl_xor_sync(~0u, sA, 4);
            sB += __shfl_xor_sync(~0u, sB, 1); sB += __shfl_xor_sync(~0u, sB, 2);
            sB += __shfl_xor_sync(~0u, sB, 4);
            float iA = 1.0f / sA, iB = 1.0f / sB;
            uint32_t h0, l0, h1, l1, h2, l2, h3, l3;
            unsigned char* ab = (unsigned char*)smem + OFF_ATT + i0 * WLD + (g << 4);
            split2(vA[0] * iA, vA[1] * iA, h0, l0); split2(vA[2] * iA, vA[3] * iA, h1, l1);
            split2(vA[4] * iA, vA[5] * iA, h2, l2); split2(vA[6] * iA, vA[7] * iA, h3, l3);
            *(uint4*)ab         = make_uint4(h0, h1, h2, h3);
            *(uint4*)(ab + 128) = make_uint4(l0, l1, l2, l3);
            ab = (unsigned char*)smem + OFF_ATT + i1 * WLD + (g << 4);
            split2(vB[0] * iB, vB[1] * iB, h0, l0); split2(vB[2] * iB, vB[3] * iB, h1, l1);
            split2(vB[4] * iB, vB[5] * iB, h2, l2); split2(vB[6] * iB, vB[7] * iB, h3, l3);
            *(uint4*)ab         = make_uint4(h0, h1, h2, h3);
            *(uint4*)(ab + 128) = make_uint4(l0, l1, l2, l3);
        }
        __syncthreads();

        // ---- aggregation on HMMA: cacc += attn @ S (3-pass split) ----
        {
            uint32_t athi[4][4], atlo[4][4];
            uint32_t tb = sb + OFF_ATT + (ib + (lid & 15)) * WLD + ((lid >> 4) << 4);
            #pragma unroll
            for (int kc = 0; kc < 4; kc++) {
                ldsm4(athi[kc], tb + kc * 32);
                ldsm4(atlo[kc], tb + 128 + kc * 32);
            }
            #pragma unroll
            for (int pass = 0; pass < 3; pass++) {
                const int sofs = (pass == 2) ? 128 : 0;
                #pragma unroll
                for (int kc = 0; kc < 4; kc++) {
                    const uint32_t* af = (pass == 1) ? atlo[kc] : athi[kc];
                    uint32_t sbB = sb + OFF_SBF + ((kc << 4) + (lid & 15)) * WLD
                                 + sofs + nh * 64 + ((lid >> 4) << 4);
                    #pragma unroll
                    for (int np = 0; np < 2; np++) {
                        uint32_t bf[4];
                        ldsm4t(bf, sbB + np * 32);
                        hmma(cacc[2 * np],     af, bf[0], bf[1]);
                        hmma(cacc[2 * np + 1], af, bf[2], bf[3]);
                    }
                }
            }
        }
        __syncthreads();
    }

    // ---- write mean over heads ----
    float* op = outp + bt * 4096;
    #pragma unroll
    for (int nt = 0; nt < 4; nt++) {
        int u = (nh << 5) + (nt << 3) + nc;
        *(float2*)&op[(ib + mr) * 64 + u]     = make_float2(0.25f * cacc[nt][0], 0.25f * cacc[nt][1]);
        *(float2*)&op[(ib + mr + 8) * 64 + u] = make_float2(0.25f * cacc[nt][2], 0.25f * cacc[nt][3]);
    }
}

extern "C" void kernel_launch(void* const* d_in, const int* in_sizes, int n_in,
                              void* d_out, int out_size) {
    const float* feat = (const float*)d_in[0];
    const int*   adj  = (const int*)d_in[1];
    const float* Wsrc = (const float*)d_in[2];
    const float* Wdst = (const float*)d_in[3];
    const float* avec = (const float*)d_in[4];

    cudaFuncSetAttribute((const void*)gat_mma_kernel,
                         cudaFuncAttributeMaxDynamicSharedMemorySize, SMEM_TOTAL);
    prep_w<<<4, 256>>>(Wsrc, Wdst);
    gat_mma_kernel<<<256, 256, SMEM_TOTAL>>>(feat, adj, avec, (float*)d_out);
}

// round 12
// speedup vs baseline: 1.2616x; 1.2616x over previous
#include <cuda_runtime.h>
#include <cuda_bf16.h>
#include <cstdint>

// GATv2 fused: B=8,T=32,N=64,F=64,U=64,H=4 (BT=256), one CTA/graph.
// Proj + agg on mma.sync.m16n8k16.bf16 (3-term split, fp32 acc).
// p/q dots + S-split fused into proj epilogue; separate pairwise/softmax (R9).

#define XLD 144
#define WLD 272
#define LDs 68
#define OFF_AX 0
#define OFF_BW 18432
#define OFF_ATT 18432            // overlay on Whi region (softmax-written)
#define OFF_SC  35840            // overlay on Wlo region (pairwise-written)
#define OFF_SF 53248
#define OFF_DT 70656
#define OFF_SBF 88064            // dedicated: written during proj epilogue
#define OFF_AS 105472
#define OFF_A8 105728
#define OFF_PS 105984
#define OFF_QS 106240
#define OFF_ADJ 106496
#define SMEM_TOTAL 107008
#define BLOBSZ 34816

__device__ __align__(256) unsigned char g_wblob[4 * BLOBSZ];

__device__ __forceinline__ uint32_t smem_u32(const void* p) {
    uint32_t a;
    asm("{ .reg .u64 t; cvta.to.shared.u64 t, %1; cvt.u32.u64 %0, t; }" : "=r"(a) : "l"(p));
    return a;
}
__device__ __forceinline__ void ldsm4(uint32_t* r, uint32_t a) {
    asm volatile("ldmatrix.sync.aligned.m8n8.x4.shared.b16 {%0,%1,%2,%3}, [%4];"
        : "=r"(r[0]), "=r"(r[1]), "=r"(r[2]), "=r"(r[3]) : "r"(a));
}
__device__ __forceinline__ void ldsm4t(uint32_t* r, uint32_t a) {
    asm volatile("ldmatrix.sync.aligned.m8n8.x4.trans.shared.b16 {%0,%1,%2,%3}, [%4];"
        : "=r"(r[0]), "=r"(r[1]), "=r"(r[2]), "=r"(r[3]) : "r"(a));
}
__device__ __forceinline__ void hmma(float* c, const uint32_t* a, uint32_t b0, uint32_t b1) {
    asm volatile("mma.sync.aligned.m16n8k16.row.col.f32.bf16.bf16.f32 "
        "{%0,%1,%2,%3}, {%4,%5,%6,%7}, {%8,%9}, {%0,%1,%2,%3};"
        : "+f"(c[0]), "+f"(c[1]), "+f"(c[2]), "+f"(c[3])
        : "r"(a[0]), "r"(a[1]), "r"(a[2]), "r"(a[3]), "r"(b0), "r"(b1));
}
__device__ __forceinline__ unsigned long long pack2(float lo, float hi) {
    unsigned long long r; asm("mov.b64 %0, {%1,%2};" : "=l"(r) : "f"(lo), "f"(hi)); return r;
}
__device__ __forceinline__ void unpack2(unsigned long long v, float& lo, float& hi) {
    asm("mov.b64 {%0,%1}, %2;" : "=f"(lo), "=f"(hi) : "l"(v));
}
__device__ __forceinline__ unsigned long long add2(unsigned long long a, unsigned long long b) {
    unsigned long long r; asm("add.rn.f32x2 %0, %1, %2;" : "=l"(r) : "l"(a), "l"(b)); return r;
}
__device__ __forceinline__ unsigned long long fma2(unsigned long long a, unsigned long long b, unsigned long long c) {
    unsigned long long r; asm("fma.rn.f32x2 %0, %1, %2, %3;" : "=l"(r) : "l"(a), "l"(b), "l"(c)); return r;
}
__device__ __forceinline__ unsigned long long relu2(unsigned long long v) {
    float lo, hi; unpack2(v, lo, hi); lo = fmaxf(lo, 0.f); hi = fmaxf(hi, 0.f); return pack2(lo, hi);
}
__device__ __forceinline__ float f4get(const float4& v, int i) {
    switch (i & 3) { case 0: return v.x; case 1: return v.y; case 2: return v.z; default: return v.w; }
}
// split (v0,v1) -> hi bf16x2 + lo bf16x2 using packed converts (RN, bit-identical)
__device__ __forceinline__ void split2(float v0, float v1, uint32_t& hw, uint32_t& lw) {
    asm("cvt.rn.bf16x2.f32 %0, %2, %1;" : "=r"(hw) : "f"(v0), "f"(v1));
    float h0 = __uint_as_float(hw << 16);
    float h1 = __uint_as_float(hw & 0xFFFF0000u);
    float r0 = v0 - h0, r1 = v1 - h1;
    asm("cvt.rn.bf16x2.f32 %0, %2, %1;" : "=r"(lw) : "f"(r0), "f"(r1));
}

__global__ void prep_w(const float* __restrict__ Ws, const float* __restrict__ Wd) {
    int h = blockIdx.x;
    unsigned char* base = g_wblob + h * BLOBSZ;
    for (int idx = threadIdx.x; idx < 64 * 128; idx += 256) {
        int k = idx >> 7, n = idx & 127;
        float w = (n < 64) ? Ws[h * 4096 + k * 64 + n] : Wd[h * 4096 + k * 64 + (n - 64)];
        __nv_bfloat16 hi = __float2bfloat16(w);
        __nv_bfloat16 lo = __float2bfloat16(w - __bfloat162float(hi));
        int byt = (k * 136 + n) * 2;
        *(unsigned short*)(base + byt)         = __bfloat16_as_ushort(hi);
        *(unsigned short*)(base + 17408 + byt) = __bfloat16_as_ushort(lo);
    }
}

__global__ void __launch_bounds__(256, 2) gat_mma_kernel(
    const float* __restrict__ feat, const int* __restrict__ adj,
    const float* __restrict__ avec, float* __restrict__ outp)
{
    extern __shared__ char smem[];
    const uint32_t sb = smem_u32(smem);   // shared-space: ONLY for ldmatrix/mma asm
    float* Sf = (float*)(smem + OFF_SF);
    float* Dt = (float*)(smem + OFF_DT);
    float* Sc = (float*)(smem + OFF_SC);
    float* aS = (float*)(smem + OFF_AS);
    float* a8 = (float*)(smem + OFF_A8);
    float* ps = (float*)(smem + OFF_PS);
    float* qs = (float*)(smem + OFF_QS);
    unsigned long long* adjb = (unsigned long long*)(smem + OFF_ADJ);

    const int tid = threadIdx.x, wid = tid >> 5, lid = tid & 31;
    const int bt = blockIdx.x, b = bt >> 5;
    const int ty = tid >> 4, tx = tid & 15;
    const int r0 = ty << 2, c0 = tx << 2;
    const int mr = lid >> 2, nc = (lid & 3) << 1;
    const int ib = (wid & 3) << 4;
    const int nh = wid >> 2;

    // ---- stage X split + adjacency ----
    {
        const float4* xp = (const float4*)(feat + bt * 4096);
        for (int idx = tid; idx < 1024; idx += 256) {
            float4 v = xp[idx];
            int i = idx >> 4, f0 = (idx & 15) << 2;
            uint32_t h01, l01, h23, l23;
            split2(v.x, v.y, h01, l01);
            split2(v.z, v.w, h23, l23);
            *(uint2*)(smem + OFF_AX + i * XLD + f0 * 2)        = make_uint2(h01, h23);
            *(uint2*)(smem + OFF_AX + (64 + i) * XLD + f0 * 2) = make_uint2(l01, l23);
        }
        if (tid < 64) {
            const int* ar = adj + b * 4096 + tid * 64;
            unsigned long long m = 1ull << tid;
            #pragma unroll 8
            for (int j = 0; j < 64; j++) if (ar[j] > 0) m |= (1ull << j);
            adjb[tid] = m;
        }
    }

    float cacc[4][4];
    #pragma unroll
    for (int t = 0; t < 4; t++) { cacc[t][0] = cacc[t][1] = cacc[t][2] = cacc[t][3] = 0.f; }

    for (int h = 0; h < 4; h++) {
        {   // ---- stage W blob + a ----
            const float4* src = (const float4*)(g_wblob + h * BLOBSZ);
            float4* dst = (float4*)(smem + OFF_BW);
            for (int k = tid; k < BLOBSZ / 16; k += 256) dst[k] = src[k];
            if (tid < 64) {
                float av = avec[h * 64 + tid];
                aS[tid] = av; a8[tid] = 0.8f * av;
            }
        }
        __syncthreads();

        // ---- projection (3-pass) + fused epilogue: Sf/Dt/SBF stores + p/q dots ----
        {
            uint32_t ahi[4][4], alo[4][4];
            uint32_t abase = sb + OFF_AX + (ib + (lid & 15)) * XLD + ((lid >> 4) << 4);
            #pragma unroll
            for (int kc = 0; kc < 4; kc++) {
                ldsm4(ahi[kc], abase + kc * 32);
                ldsm4(alo[kc], abase + 64 * XLD + kc * 32);
            }
            float pacc[8][4];
            #pragma unroll
            for (int t = 0; t < 8; t++) { pacc[t][0] = pacc[t][1] = pacc[t][2] = pacc[t][3] = 0.f; }
            #pragma unroll
            for (int pass = 0; pass < 3; pass++) {
                const int wofs = (pass == 2) ? 17408 : 0;
                #pragma unroll
                for (int kc = 0; kc < 4; kc++) {
                    const uint32_t* af = (pass == 1) ? alo[kc] : ahi[kc];
                    uint32_t wb = sb + OFF_BW + wofs + ((kc << 4) + (lid & 15)) * WLD
                                + nh * 128 + ((lid >> 4) << 4);
                    #pragma unroll
                    for (int np = 0; np < 4; np++) {
                        uint32_t bf[4];
                        ldsm4t(bf, wb + np * 32);
                        hmma(pacc[2 * np],     af, bf[0], bf[1]);
                        hmma(pacc[2 * np + 1], af, bf[2], bf[3]);
                    }
                }
            }
            float va = 0.f, vb = 0.f;
            if (nh == 0) {      // S rows: fp32 + bf16-split + p-dot
                #pragma unroll
                for (int nt = 0; nt < 8; nt++) {
                    int u = (nt << 3) + nc;
                    float2 av = *(const float2*)&aS[u];
                    va += av.x * pacc[nt][0] + av.y * pacc[nt][1];
                    vb += av.x * pacc[nt][2] + av.y * pacc[nt][3];
                    *(float2*)&Sf[(ib + mr) * LDs + u]     = make_float2(pacc[nt][0], pacc[nt][1]);
                    *(float2*)&Sf[(ib + mr + 8) * LDs + u] = make_float2(pacc[nt][2], pacc[nt][3]);
                    uint32_t hw, lw;
                    split2(pacc[nt][0], pacc[nt][1], hw, lw);
                    *(uint32_t*)(smem + OFF_SBF + (ib + mr) * WLD + (u << 1))       = hw;
                    *(uint32_t*)(smem + OFF_SBF + (ib + mr) * WLD + 128 + (u << 1)) = lw;
                    split2(pacc[nt][2], pacc[nt][3], hw, lw);
                    *(uint32_t*)(smem + OFF_SBF + (ib + mr + 8) * WLD + (u << 1))       = hw;
                    *(uint32_t*)(smem + OFF_SBF + (ib + mr + 8) * WLD + 128 + (u << 1)) = lw;
                }
            } else {            // D rows -> transposed Dt + q-dot
                #pragma unroll
                for (int nt = 0; nt < 8; nt++) {
                    int u = (nt << 3) + nc;
                    float2 av = *(const float2*)&aS[u];
                    va += av.x * pacc[nt][0] + av.y * pacc[nt][1];
                    vb += av.x * pacc[nt][2] + av.y * pacc[nt][3];
                    Dt[u * LDs + ib + mr]           = pacc[nt][0];
                    Dt[(u + 1) * LDs + ib + mr]     = pacc[nt][1];
                    Dt[u * LDs + ib + mr + 8]       = pacc[nt][2];
                    Dt[(u + 1) * LDs + ib + mr + 8] = pacc[nt][3];
                }
            }
            va += __shfl_xor_sync(~0u, va, 1); va += __shfl_xor_sync(~0u, va, 2);
            vb += __shfl_xor_sync(~0u, vb, 1); vb += __shfl_xor_sync(~0u, vb, 2);
            if ((lid & 3) == 0) {
                if (nh == 0) { ps[ib + mr] = va; ps[ib + mr + 8] = vb; }
                else         { qs[ib + mr] = va; qs[ib + mr + 8] = vb; }
            }
        }
        __syncthreads();

        // ---- pairwise: 0.2*(p_i+q_j) + sum_u 0.8*a_u*relu(s_iu+d_ju) -> Sc ----
        {
            unsigned long long acc0[4], acc1[4];
            #pragma unroll
            for (int ii = 0; ii < 4; ii++) { acc0[ii] = 0ull; acc1[ii] = 0ull; }
            #pragma unroll 2
            for (int u4 = 0; u4 < 64; u4 += 4) {
                float4 a84 = *(const float4*)&a8[u4];
                float4 s0 = *(const float4*)&Sf[(r0 + 0) * LDs + u4];
                float4 s1 = *(const float4*)&Sf[(r0 + 1) * LDs + u4];
                float4 s2 = *(const float4*)&Sf[(r0 + 2) * LDs + u4];
                float4 s3 = *(const float4*)&Sf[(r0 + 3) * LDs + u4];
                #pragma unroll
                for (int uu = 0; uu < 4; uu++) {
                    ulonglong2 d2 = *(const ulonglong2*)&Dt[(u4 + uu) * LDs + c0];
                    float a8u = f4get(a84, uu);
                    unsigned long long a2 = pack2(a8u, a8u);
#define PR(K, SR) { float s_ = f4get(SR, uu); unsigned long long s2_ = pack2(s_, s_); \
                    acc0[K] = fma2(a2, relu2(add2(s2_, d2.x)), acc0[K]);              \
                    acc1[K] = fma2(a2, relu2(add2(s2_, d2.y)), acc1[K]); }
                    PR(0, s0) PR(1, s1) PR(2, s2) PR(3, s3)
#undef PR
                }
            }
            float q0 = qs[c0], q1 = qs[c0 + 1], q2 = qs[c0 + 2], q3 = qs[c0 + 3];
            #pragma unroll
            for (int ii = 0; ii < 4; ii++) {
                float pi = ps[r0 + ii], v0, v1, v2, v3;
                unpack2(acc0[ii], v0, v1); unpack2(acc1[ii], v2, v3);
                float4 sc;
                sc.x = 0.2f * (pi + q0) + v0; sc.y = 0.2f * (pi + q1) + v1;
                sc.z = 0.2f * (pi + q2) + v2; sc.w = 0.2f * (pi + q3) + v3;
                *(float4*)&Sc[(r0 + ii) * LDs + c0] = sc;
            }
        }
        __syncthreads();

        // ---- masked softmax (4 threads/row) -> emit attn bf16 split (ATT) ----
        {
            int row = tid >> 2, qd = tid & 3;
            const float* srow = Sc + row * LDs + (qd << 4);
            unsigned mb = (unsigned)(adjb[row] >> (qd << 4)) & 0xFFFFu;
            float vals[16], mx = -3.0e38f;
            #pragma unroll
            for (int c = 0; c < 16; c++) {
                float v = ((mb >> c) & 1u) ? srow[c] : -1e9f;
                vals[c] = v; mx = fmaxf(mx, v);
            }
            mx = fmaxf(mx, __shfl_xor_sync(~0u, mx, 1));
            mx = fmaxf(mx, __shfl_xor_sync(~0u, mx, 2));
            float ssum = 0.f;
            #pragma unroll
            for (int c = 0; c < 16; c++) {
                float e = exp2f((vals[c] - mx) * 1.4426950408889634f);
                vals[c] = e; ssum += e;
            }
            ssum += __shfl_xor_sync(~0u, ssum, 1);
            ssum += __shfl_xor_sync(~0u, ssum, 2);
            float inv = 1.0f / ssum;
            unsigned char* at_row = (unsigned char*)smem + OFF_ATT + row * WLD + (qd << 5);
            #pragma unroll
            for (int c = 0; c < 16; c += 2) {
                uint32_t hw, lw;
                split2(vals[c] * inv, vals[c + 1] * inv, hw, lw);
                *(uint32_t*)(at_row + c * 2)       = hw;
                *(uint32_t*)(at_row + 128 + c * 2) = lw;
            }
        }
        __syncthreads();

        // ---- aggregation on HMMA: cacc += attn @ S (3-pass split) ----
        {
            uint32_t athi[4][4], atlo[4][4];
            uint32_t tb = sb + OFF_ATT + (ib + (lid & 15)) * WLD + ((lid >> 4) << 4);
            #pragma unroll
            for (int kc = 0; kc < 4; kc++) {
                ldsm4(athi[kc], tb + kc * 32);
                ldsm4(atlo[kc], tb + 128 + kc * 32);
            }
            #pragma unroll
            for (int pass = 0; pass < 3; pass++) {
                const int sofs = (pass == 2) ? 128 : 0;
                #pragma unroll
                for (int kc = 0; kc < 4; kc++) {
                    const uint32_t* af = (pass == 1) ? atlo[kc] : athi[kc];
                    uint32_t sbB = sb + OFF_SBF + ((kc << 4) + (lid & 15)) * WLD
                                 + sofs + nh * 64 + ((lid >> 4) << 4);
                    #pragma unroll
                    for (int np = 0; np < 2; np++) {
                        uint32_t bf[4];
                        ldsm4t(bf, sbB + np * 32);
                        hmma(cacc[2 * np],     af, bf[0], bf[1]);
                        hmma(cacc[2 * np + 1], af, bf[2], bf[3]);
                    }
                }
            }
        }
        __syncthreads();
    }

    // ---- write mean over heads ----
    float* op = outp + bt * 4096;
    #pragma unroll
    for (int nt = 0; nt < 4; nt++) {
        int u = (nh << 5) + (nt << 3) + nc;
        *(float2*)&op[(ib + mr) * 64 + u]     = make_float2(0.25f * cacc[nt][0], 0.25f * cacc[nt][1]);
        *(float2*)&op[(ib + mr + 8) * 64 + u] = make_float2(0.25f * cacc[nt][2], 0.25f * cacc[nt][3]);
    }
}

extern "C" void kernel_launch(void* const* d_in, const int* in_sizes, int n_in,
                              void* d_out, int out_size) {
    const float* feat = (const float*)d_in[0];
    const int*   adj  = (const int*)d_in[1];
    const float* Wsrc = (const float*)d_in[2];
    const float* Wdst = (const float*)d_in[3];
    const float* avec = (const float*)d_in[4];

    cudaFuncSetAttribute((const void*)gat_mma_kernel,
                         cudaFuncAttributeMaxDynamicSharedMemorySize, SMEM_TOTAL);
    prep_w<<<4, 256>>>(Wsrc, Wdst);
    gat_mma_kernel<<<256, 256, SMEM_TOTAL>>>(feat, adj, avec, (float*)d_out);
}

// round 13
// speedup vs baseline: 1.3004x; 1.0307x over previous
#include <cuda_runtime.h>
#include <cuda_bf16.h>
#include <cstdint>

// GATv2 fused: B=8,T=32,N=64,F=64,U=64,H=4 (BT=256), one CTA/graph.
// Proj + agg on mma.sync.m16n8k16.bf16 (3-term split, fp32 acc), B-fragment
// shared across hi/lo A passes. p/q + S-split fused into proj epilogue.

#define XLD 144
#define WLD 272
#define LDs 68
#define OFF_AX 0
#define OFF_BW 18432
#define OFF_ATT 18432            // overlay on Whi region (softmax-written)
#define OFF_SC  35840            // overlay on Wlo region (pairwise-written)
#define OFF_SF 53248
#define OFF_DT 70656
#define OFF_SBF 88064            // dedicated: written during proj epilogue
#define OFF_AS 105472
#define OFF_A8 105728
#define OFF_PS 105984
#define OFF_QS 106240
#define OFF_ADJ 106496
#define SMEM_TOTAL 107008
#define BLOBSZ 34816

__device__ __align__(256) unsigned char g_wblob[4 * BLOBSZ];

__device__ __forceinline__ uint32_t smem_u32(const void* p) {
    uint32_t a;
    asm("{ .reg .u64 t; cvta.to.shared.u64 t, %1; cvt.u32.u64 %0, t; }" : "=r"(a) : "l"(p));
    return a;
}
__device__ __forceinline__ void ldsm4(uint32_t* r, uint32_t a) {
    asm volatile("ldmatrix.sync.aligned.m8n8.x4.shared.b16 {%0,%1,%2,%3}, [%4];"
        : "=r"(r[0]), "=r"(r[1]), "=r"(r[2]), "=r"(r[3]) : "r"(a));
}
__device__ __forceinline__ void ldsm4t(uint32_t* r, uint32_t a) {
    asm volatile("ldmatrix.sync.aligned.m8n8.x4.trans.shared.b16 {%0,%1,%2,%3}, [%4];"
        : "=r"(r[0]), "=r"(r[1]), "=r"(r[2]), "=r"(r[3]) : "r"(a));
}
__device__ __forceinline__ void hmma(float* c, const uint32_t* a, uint32_t b0, uint32_t b1) {
    asm volatile("mma.sync.aligned.m16n8k16.row.col.f32.bf16.bf16.f32 "
        "{%0,%1,%2,%3}, {%4,%5,%6,%7}, {%8,%9}, {%0,%1,%2,%3};"
        : "+f"(c[0]), "+f"(c[1]), "+f"(c[2]), "+f"(c[3])
        : "r"(a[0]), "r"(a[1]), "r"(a[2]), "r"(a[3]), "r"(b0), "r"(b1));
}
__device__ __forceinline__ unsigned long long pack2(float lo, float hi) {
    unsigned long long r; asm("mov.b64 %0, {%1,%2};" : "=l"(r) : "f"(lo), "f"(hi)); return r;
}
__device__ __forceinline__ void unpack2(unsigned long long v, float& lo, float& hi) {
    asm("mov.b64 {%0,%1}, %2;" : "=f"(lo), "=f"(hi) : "l"(v));
}
__device__ __forceinline__ unsigned long long add2(unsigned long long a, unsigned long long b) {
    unsigned long long r; asm("add.rn.f32x2 %0, %1, %2;" : "=l"(r) : "l"(a), "l"(b)); return r;
}
__device__ __forceinline__ unsigned long long fma2(unsigned long long a, unsigned long long b, unsigned long long c) {
    unsigned long long r; asm("fma.rn.f32x2 %0, %1, %2, %3;" : "=l"(r) : "l"(a), "l"(b), "l"(c)); return r;
}
__device__ __forceinline__ unsigned long long relu2(unsigned long long v) {
    float lo, hi; unpack2(v, lo, hi); lo = fmaxf(lo, 0.f); hi = fmaxf(hi, 0.f); return pack2(lo, hi);
}
__device__ __forceinline__ float f4get(const float4& v, int i) {
    switch (i & 3) { case 0: return v.x; case 1: return v.y; case 2: return v.z; default: return v.w; }
}
__device__ __forceinline__ void split2(float v0, float v1, uint32_t& hw, uint32_t& lw) {
    asm("cvt.rn.bf16x2.f32 %0, %2, %1;" : "=r"(hw) : "f"(v0), "f"(v1));
    float h0 = __uint_as_float(hw << 16);
    float h1 = __uint_as_float(hw & 0xFFFF0000u);
    float r0 = v0 - h0, r1 = v1 - h1;
    asm("cvt.rn.bf16x2.f32 %0, %2, %1;" : "=r"(lw) : "f"(r0), "f"(r1));
}

__global__ void prep_w(const float* __restrict__ Ws, const float* __restrict__ Wd) {
    int h = blockIdx.x;
    unsigned char* base = g_wblob + h * BLOBSZ;
    for (int idx = threadIdx.x; idx < 64 * 128; idx += 256) {
        int k = idx >> 7, n = idx & 127;
        float w = (n < 64) ? Ws[h * 4096 + k * 64 + n] : Wd[h * 4096 + k * 64 + (n - 64)];
        __nv_bfloat16 hi = __float2bfloat16(w);
        __nv_bfloat16 lo = __float2bfloat16(w - __bfloat162float(hi));
        int byt = (k * 136 + n) * 2;
        *(unsigned short*)(base + byt)         = __bfloat16_as_ushort(hi);
        *(unsigned short*)(base + 17408 + byt) = __bfloat16_as_ushort(lo);
    }
}

__global__ void __launch_bounds__(256, 2) gat_mma_kernel(
    const float* __restrict__ feat, const int* __restrict__ adj,
    const float* __restrict__ avec, float* __restrict__ outp)
{
    extern __shared__ char smem[];
    const uint32_t sb = smem_u32(smem);   // shared-space: ONLY for ldmatrix/mma asm
    float* Sf = (float*)(smem + OFF_SF);
    float* Dt = (float*)(smem + OFF_DT);
    float* Sc = (float*)(smem + OFF_SC);
    float* aS = (float*)(smem + OFF_AS);
    float* a8 = (float*)(smem + OFF_A8);
    float* ps = (float*)(smem + OFF_PS);
    float* qs = (float*)(smem + OFF_QS);
    unsigned long long* adjb = (unsigned long long*)(smem + OFF_ADJ);

    const int tid = threadIdx.x, wid = tid >> 5, lid = tid & 31;
    const int bt = blockIdx.x, b = bt >> 5;
    const int ty = tid >> 4, tx = tid & 15;
    const int r0 = ty << 2, c0 = tx << 2;
    const int mr = lid >> 2, nc = (lid & 3) << 1;
    const int ib = (wid & 3) << 4;
    const int nh = wid >> 2;

    // ---- stage X split + adjacency ----
    {
        const float4* xp = (const float4*)(feat + bt * 4096);
        for (int idx = tid; idx < 1024; idx += 256) {
            float4 v = xp[idx];
            int i = idx >> 4, f0 = (idx & 15) << 2;
            uint32_t h01, l01, h23, l23;
            split2(v.x, v.y, h01, l01);
            split2(v.z, v.w, h23, l23);
            *(uint2*)(smem + OFF_AX + i * XLD + f0 * 2)        = make_uint2(h01, h23);
            *(uint2*)(smem + OFF_AX + (64 + i) * XLD + f0 * 2) = make_uint2(l01, l23);
        }
        if (tid < 64) {
            const int* ar = adj + b * 4096 + tid * 64;
            unsigned long long m = 1ull << tid;
            #pragma unroll 8
            for (int j = 0; j < 64; j++) if (ar[j] > 0) m |= (1ull << j);
            adjb[tid] = m;
        }
    }

    float cacc[4][4];
    #pragma unroll
    for (int t = 0; t < 4; t++) { cacc[t][0] = cacc[t][1] = cacc[t][2] = cacc[t][3] = 0.f; }

    for (int h = 0; h < 4; h++) {
        {   // ---- stage W blob + a ----
            const float4* src = (const float4*)(g_wblob + h * BLOBSZ);
            float4* dst = (float4*)(smem + OFF_BW);
            for (int k = tid; k < BLOBSZ / 16; k += 256) dst[k] = src[k];
            if (tid < 64) {
                float av = avec[h * 64 + tid];
                aS[tid] = av; a8[tid] = 0.8f * av;
            }
        }
        __syncthreads();

        // ---- projection: shared-B passes (Whi x {ahi,alo}) then (Wlo x ahi) ----
        {
            uint32_t ahi[4][4], alo[4][4];
            uint32_t abase = sb + OFF_AX + (ib + (lid & 15)) * XLD + ((lid >> 4) << 4);
            #pragma unroll
            for (int kc = 0; kc < 4; kc++) {
                ldsm4(ahi[kc], abase + kc * 32);
                ldsm4(alo[kc], abase + 64 * XLD + kc * 32);
            }
            float pacc[8][4];
            #pragma unroll
            for (int t = 0; t < 8; t++) { pacc[t][0] = pacc[t][1] = pacc[t][2] = pacc[t][3] = 0.f; }
            #pragma unroll
            for (int kc = 0; kc < 4; kc++) {   // Whi: 2 hmma per fragment
                uint32_t wb = sb + OFF_BW + ((kc << 4) + (lid & 15)) * WLD
                            + nh * 128 + ((lid >> 4) << 4);
                #pragma unroll
                for (int np = 0; np < 4; np++) {
                    uint32_t bf[4];
                    ldsm4t(bf, wb + np * 32);
                    hmma(pacc[2 * np],     ahi[kc], bf[0], bf[1]);
                    hmma(pacc[2 * np + 1], ahi[kc], bf[2], bf[3]);
                    hmma(pacc[2 * np],     alo[kc], bf[0], bf[1]);
                    hmma(pacc[2 * np + 1], alo[kc], bf[2], bf[3]);
                }
            }
            #pragma unroll
            for (int kc = 0; kc < 4; kc++) {   // Wlo: ahi only
                uint32_t wb = sb + OFF_BW + 17408 + ((kc << 4) + (lid & 15)) * WLD
                            + nh * 128 + ((lid >> 4) << 4);
                #pragma unroll
                for (int np = 0; np < 4; np++) {
                    uint32_t bf[4];
                    ldsm4t(bf, wb + np * 32);
                    hmma(pacc[2 * np],     ahi[kc], bf[0], bf[1]);
                    hmma(pacc[2 * np + 1], ahi[kc], bf[2], bf[3]);
                }
            }
            float va = 0.f, vb = 0.f;
            if (nh == 0) {      // S rows: fp32 + bf16-split + p-dot
                #pragma unroll
                for (int nt = 0; nt < 8; nt++) {
                    int u = (nt << 3) + nc;
                    float2 av = *(const float2*)&aS[u];
                    va += av.x * pacc[nt][0] + av.y * pacc[nt][1];
                    vb += av.x * pacc[nt][2] + av.y * pacc[nt][3];
                    *(float2*)&Sf[(ib + mr) * LDs + u]     = make_float2(pacc[nt][0], pacc[nt][1]);
                    *(float2*)&Sf[(ib + mr + 8) * LDs + u] = make_float2(pacc[nt][2], pacc[nt][3]);
                    uint32_t hw, lw;
                    split2(pacc[nt][0], pacc[nt][1], hw, lw);
                    *(uint32_t*)(smem + OFF_SBF + (ib + mr) * WLD + (u << 1))       = hw;
                    *(uint32_t*)(smem + OFF_SBF + (ib + mr) * WLD + 128 + (u << 1)) = lw;
                    split2(pacc[nt][2], pacc[nt][3], hw, lw);
                    *(uint32_t*)(smem + OFF_SBF + (ib + mr + 8) * WLD + (u << 1))       = hw;
                    *(uint32_t*)(smem + OFF_SBF + (ib + mr + 8) * WLD + 128 + (u << 1)) = lw;
                }
            } else {            // D rows -> transposed Dt + q-dot
                #pragma unroll
                for (int nt = 0; nt < 8; nt++) {
                    int u = (nt << 3) + nc;
                    float2 av = *(const float2*)&aS[u];
                    va += av.x * pacc[nt][0] + av.y * pacc[nt][1];
                    vb += av.x * pacc[nt][2] + av.y * pacc[nt][3];
                    Dt[u * LDs + ib + mr]           = pacc[nt][0];
                    Dt[(u + 1) * LDs + ib + mr]     = pacc[nt][1];
                    Dt[u * LDs + ib + mr + 8]       = pacc[nt][2];
                    Dt[(u + 1) * LDs + ib + mr + 8] = pacc[nt][3];
                }
            }
            va += __shfl_xor_sync(~0u, va, 1); va += __shfl_xor_sync(~0u, va, 2);
            vb += __shfl_xor_sync(~0u, vb, 1); vb += __shfl_xor_sync(~0u, vb, 2);
            if ((lid & 3) == 0) {
                if (nh == 0) { ps[ib + mr] = va; ps[ib + mr + 8] = vb; }
                else         { qs[ib + mr] = va; qs[ib + mr + 8] = vb; }
            }
        }
        __syncthreads();

        // ---- pairwise: 0.2*(p_i+q_j) + sum_u 0.8*a_u*relu(s_iu+d_ju) -> Sc ----
        {
            unsigned long long acc0[4], acc1[4];
            #pragma unroll
            for (int ii = 0; ii < 4; ii++) { acc0[ii] = 0ull; acc1[ii] = 0ull; }
            #pragma unroll 2
            for (int u4 = 0; u4 < 64; u4 += 4) {
                float4 a84 = *(const float4*)&a8[u4];
                float4 s0 = *(const float4*)&Sf[(r0 + 0) * LDs + u4];
                float4 s1 = *(const float4*)&Sf[(r0 + 1) * LDs + u4];
                float4 s2 = *(const float4*)&Sf[(r0 + 2) * LDs + u4];
                float4 s3 = *(const float4*)&Sf[(r0 + 3) * LDs + u4];
                #pragma unroll
                for (int uu = 0; uu < 4; uu++) {
                    ulonglong2 d2 = *(const ulonglong2*)&Dt[(u4 + uu) * LDs + c0];
                    float a8u = f4get(a84, uu);
                    unsigned long long a2 = pack2(a8u, a8u);
#define PR(K, SR) { float s_ = f4get(SR, uu); unsigned long long s2_ = pack2(s_, s_); \
                    acc0[K] = fma2(a2, relu2(add2(s2_, d2.x)), acc0[K]);              \
                    acc1[K] = fma2(a2, relu2(add2(s2_, d2.y)), acc1[K]); }
                    PR(0, s0) PR(1, s1) PR(2, s2) PR(3, s3)
#undef PR
                }
            }
            float q0 = qs[c0], q1 = qs[c0 + 1], q2 = qs[c0 + 2], q3 = qs[c0 + 3];
            #pragma unroll
            for (int ii = 0; ii < 4; ii++) {
                float pi = ps[r0 + ii], v0, v1, v2, v3;
                unpack2(acc0[ii], v0, v1); unpack2(acc1[ii], v2, v3);
                float4 sc;
                sc.x = 0.2f * (pi + q0) + v0; sc.y = 0.2f * (pi + q1) + v1;
                sc.z = 0.2f * (pi + q2) + v2; sc.w = 0.2f * (pi + q3) + v3;
                *(float4*)&Sc[(r0 + ii) * LDs + c0] = sc;
            }
        }
        __syncthreads();

        // ---- masked softmax (4 threads/row) -> emit attn bf16 split (ATT) ----
        {
            int row = tid >> 2, qd = tid & 3;
            const float* srow = Sc + row * LDs + (qd << 4);
            unsigned mb = (unsigned)(adjb[row] >> (qd << 4)) & 0xFFFFu;
            float vals[16], mx = -3.0e38f;
            #pragma unroll
            for (int c = 0; c < 16; c++) {
                float v = ((mb >> c) & 1u) ? srow[c] : -1e9f;
                vals[c] = v; mx = fmaxf(mx, v);
            }
            mx = fmaxf(mx, __shfl_xor_sync(~0u, mx, 1));
            mx = fmaxf(mx, __shfl_xor_sync(~0u, mx, 2));
            float ssum = 0.f;
            #pragma unroll
            for (int c = 0; c < 16; c++) {
                float e = exp2f((vals[c] - mx) * 1.4426950408889634f);
                vals[c] = e; ssum += e;
            }
            ssum += __shfl_xor_sync(~0u, ssum, 1);
            ssum += __shfl_xor_sync(~0u, ssum, 2);
            float inv = 1.0f / ssum;
            unsigned char* at_row = (unsigned char*)smem + OFF_ATT + row * WLD + (qd << 5);
            #pragma unroll
            for (int c = 0; c < 16; c += 2) {
                uint32_t hw, lw;
                split2(vals[c] * inv, vals[c + 1] * inv, hw, lw);
                *(uint32_t*)(at_row + c * 2)       = hw;
                *(uint32_t*)(at_row + 128 + c * 2) = lw;
            }
        }
        __syncthreads();

        // ---- aggregation: shared-B passes (S_hi x {athi,atlo}) then (S_lo x athi) ----
        {
            uint32_t athi[4][4], atlo[4][4];
            uint32_t tb = sb + OFF_ATT + (ib + (lid & 15)) * WLD + ((lid >> 4) << 4);
            #pragma unroll
            for (int kc = 0; kc < 4; kc++) {
                ldsm4(athi[kc], tb + kc * 32);
                ldsm4(atlo[kc], tb + 128 + kc * 32);
            }
            #pragma unroll
            for (int kc = 0; kc < 4; kc++) {   // S_hi: 2 hmma per fragment
                uint32_t sbB = sb + OFF_SBF + ((kc << 4) + (lid & 15)) * WLD
                             + nh * 64 + ((lid >> 4) << 4);
                #pragma unroll
                for (int np = 0; np < 2; np++) {
                    uint32_t bf[4];
                    ldsm4t(bf, sbB + np * 32);
                    hmma(cacc[2 * np],     athi[kc], bf[0], bf[1]);
                    hmma(cacc[2 * np + 1], athi[kc], bf[2], bf[3]);
                    hmma(cacc[2 * np],     atlo[kc], bf[0], bf[1]);
                    hmma(cacc[2 * np + 1], atlo[kc], bf[2], bf[3]);
                }
            }
            #pragma unroll
            for (int kc = 0; kc < 4; kc++) {   // S_lo: athi only
                uint32_t sbB = sb + OFF_SBF + ((kc << 4) + (lid & 15)) * WLD
                             + 128 + nh * 64 + ((lid >> 4) << 4);
                #pragma unroll
                for (int np = 0; np < 2; np++) {
                    uint32_t bf[4];
                    ldsm4t(bf, sbB + np * 32);
                    hmma(cacc[2 * np],     athi[kc], bf[0], bf[1]);
                    hmma(cacc[2 * np + 1], athi[kc], bf[2], bf[3]);
                }
            }
        }
        __syncthreads();
    }

    // ---- write mean over heads ----
    float* op = outp + bt * 4096;
    #pragma unroll
    for (int nt = 0; nt < 4; nt++) {
        int u = (nh << 5) + (nt << 3) + nc;
        *(float2*)&op[(ib + mr) * 64 + u]     = make_float2(0.25f * cacc[nt][0], 0.25f * cacc[nt][1]);
        *(float2*)&op[(ib + mr + 8) * 64 + u] = make_float2(0.25f * cacc[nt][2], 0.25f * cacc[nt][3]);
    }
}

extern "C" void kernel_launch(void* const* d_in, const int* in_sizes, int n_in,
                              void* d_out, int out_size) {
    const float* feat = (const float*)d_in[0];
    const int*   adj  = (const int*)d_in[1];
    const float* Wsrc = (const float*)d_in[2];
    const float* Wdst = (const float*)d_in[3];
    const float* avec = (const float*)d_in[4];

    cudaFuncSetAttribute((const void*)gat_mma_kernel,
                         cudaFuncAttributeMaxDynamicSharedMemorySize, SMEM_TOTAL);
    prep_w<<<4, 256>>>(Wsrc, Wdst);
    gat_mma_kernel<<<256, 256, SMEM_TOTAL>>>(feat, adj, avec, (float*)d_out);
}

// round 16
// speedup vs baseline: 1.3294x; 1.0224x over previous
#include <cuda_runtime.h>
#include <cuda_bf16.h>
#include <cstdint>

// GATv2 fused: B=8,T=32,N=64,F=64,U=64,H=4 (BT=256), one CTA/graph.
// Proj + agg on mma.sync.m16n8k16.bf16 (3-term split, fp32 acc), B-fragment
// shared across hi/lo A passes. p/q + S-split fused into proj epilogue.
// Pairwise + masked softmax fused in registers (4x4 tile, 16-lane shfl).

#define XLD 144
#define WLD 272
#define LDs 68
#define OFF_AX 0
#define OFF_BW 18432
#define OFF_ATT 18432            // overlay on Whi region (softmax-written)
#define OFF_SF 53248
#define OFF_DT 70656
#define OFF_SBF 88064            // dedicated: written during proj epilogue
#define OFF_AS 105472
#define OFF_A8 105728
#define OFF_PS 105984
#define OFF_QS 106240
#define OFF_ADJ 106496
#define SMEM_TOTAL 107008
#define BLOBSZ 34816

__device__ __align__(256) unsigned char g_wblob[4 * BLOBSZ];

__device__ __forceinline__ uint32_t smem_u32(const void* p) {
    uint32_t a;
    asm("{ .reg .u64 t; cvta.to.shared.u64 t, %1; cvt.u32.u64 %0, t; }" : "=r"(a) : "l"(p));
    return a;
}
__device__ __forceinline__ void ldsm4(uint32_t* r, uint32_t a) {
    asm volatile("ldmatrix.sync.aligned.m8n8.x4.shared.b16 {%0,%1,%2,%3}, [%4];"
        : "=r"(r[0]), "=r"(r[1]), "=r"(r[2]), "=r"(r[3]) : "r"(a));
}
__device__ __forceinline__ void ldsm4t(uint32_t* r, uint32_t a) {
    asm volatile("ldmatrix.sync.aligned.m8n8.x4.trans.shared.b16 {%0,%1,%2,%3}, [%4];"
        : "=r"(r[0]), "=r"(r[1]), "=r"(r[2]), "=r"(r[3]) : "r"(a));
}
__device__ __forceinline__ void hmma(float* c, const uint32_t* a, uint32_t b0, uint32_t b1) {
    asm volatile("mma.sync.aligned.m16n8k16.row.col.f32.bf16.bf16.f32 "
        "{%0,%1,%2,%3}, {%4,%5,%6,%7}, {%8,%9}, {%0,%1,%2,%3};"
        : "+f"(c[0]), "+f"(c[1]), "+f"(c[2]), "+f"(c[3])
        : "r"(a[0]), "r"(a[1]), "r"(a[2]), "r"(a[3]), "r"(b0), "r"(b1));
}
__device__ __forceinline__ unsigned long long pack2(float lo, float hi) {
    unsigned long long r; asm("mov.b64 %0, {%1,%2};" : "=l"(r) : "f"(lo), "f"(hi)); return r;
}
__device__ __forceinline__ void unpack2(unsigned long long v, float& lo, float& hi) {
    asm("mov.b64 {%0,%1}, %2;" : "=f"(lo), "=f"(hi) : "l"(v));
}
__device__ __forceinline__ unsigned long long add2(unsigned long long a, unsigned long long b) {
    unsigned long long r; asm("add.rn.f32x2 %0, %1, %2;" : "=l"(r) : "l"(a), "l"(b)); return r;
}
__device__ __forceinline__ unsigned long long fma2(unsigned long long a, unsigned long long b, unsigned long long c) {
    unsigned long long r; asm("fma.rn.f32x2 %0, %1, %2, %3;" : "=l"(r) : "l"(a), "l"(b), "l"(c)); return r;
}
// relu on both halves (FMNMX pair; proven)
__device__ __forceinline__ unsigned long long relu2(unsigned long long v) {
    float lo, hi; unpack2(v, lo, hi); lo = fmaxf(lo, 0.f); hi = fmaxf(hi, 0.f); return pack2(lo, hi);
}
__device__ __forceinline__ float f4get(const float4& v, int i) {
    switch (i & 3) { case 0: return v.x; case 1: return v.y; case 2: return v.z; default: return v.w; }
}
__device__ __forceinline__ void split2(float v0, float v1, uint32_t& hw, uint32_t& lw) {
    asm("cvt.rn.bf16x2.f32 %0, %2, %1;" : "=r"(hw) : "f"(v0), "f"(v1));
    float h0 = __uint_as_float(hw << 16);
    float h1 = __uint_as_float(hw & 0xFFFF0000u);
    float r0 = v0 - h0, r1 = v1 - h1;
    asm("cvt.rn.bf16x2.f32 %0, %2, %1;" : "=r"(lw) : "f"(r0), "f"(r1));
}

__global__ void prep_w(const float* __restrict__ Ws, const float* __restrict__ Wd) {
    int h = blockIdx.x;
    unsigned char* base = g_wblob + h * BLOBSZ;
    for (int idx = threadIdx.x; idx < 64 * 128; idx += 256) {
        int k = idx >> 7, n = idx & 127;
        float w = (n < 64) ? Ws[h * 4096 + k * 64 + n] : Wd[h * 4096 + k * 64 + (n - 64)];
        __nv_bfloat16 hi = __float2bfloat16(w);
        __nv_bfloat16 lo = __float2bfloat16(w - __bfloat162float(hi));
        int byt = (k * 136 + n) * 2;
        *(unsigned short*)(base + byt)         = __bfloat16_as_ushort(hi);
        *(unsigned short*)(base + 17408 + byt) = __bfloat16_as_ushort(lo);
    }
}

__global__ void __launch_bounds__(256, 2) gat_mma_kernel(
    const float* __restrict__ feat, const int* __restrict__ adj,
    const float* __restrict__ avec, float* __restrict__ outp)
{
    extern __shared__ char smem[];
    const uint32_t sb = smem_u32(smem);   // shared-space: ONLY for ldmatrix/mma asm
    float* Sf = (float*)(smem + OFF_SF);
    float* Dt = (float*)(smem + OFF_DT);
    float* aS = (float*)(smem + OFF_AS);
    float* a8 = (float*)(smem + OFF_A8);
    float* ps = (float*)(smem + OFF_PS);
    float* qs = (float*)(smem + OFF_QS);
    unsigned long long* adjb = (unsigned long long*)(smem + OFF_ADJ);

    const int tid = threadIdx.x, wid = tid >> 5, lid = tid & 31;
    const int bt = blockIdx.x, b = bt >> 5;
    const int ty = tid >> 4, tx = tid & 15;
    const int r0 = ty << 2, c0 = tx << 2;
    const int mr = lid >> 2, nc = (lid & 3) << 1;
    const int ib = (wid & 3) << 4;
    const int nh = wid >> 2;

    // ---- stage X split + adjacency ----
    {
        const float4* xp = (const float4*)(feat + bt * 4096);
        for (int idx = tid; idx < 1024; idx += 256) {
            float4 v = xp[idx];
            int i = idx >> 4, f0 = (idx & 15) << 2;
            uint32_t h01, l01, h23, l23;
            split2(v.x, v.y, h01, l01);
            split2(v.z, v.w, h23, l23);
            *(uint2*)(smem + OFF_AX + i * XLD + f0 * 2)        = make_uint2(h01, h23);
            *(uint2*)(smem + OFF_AX + (64 + i) * XLD + f0 * 2) = make_uint2(l01, l23);
        }
        if (tid < 64) {
            const int* ar = adj + b * 4096 + tid * 64;
            unsigned long long m = 1ull << tid;
            #pragma unroll 8
            for (int j = 0; j < 64; j++) if (ar[j] > 0) m |= (1ull << j);
            adjb[tid] = m;
        }
    }

    float cacc[4][4];
    #pragma unroll
    for (int t = 0; t < 4; t++) { cacc[t][0] = cacc[t][1] = cacc[t][2] = cacc[t][3] = 0.f; }

    for (int h = 0; h < 4; h++) {
        {   // ---- stage W blob + a ----
            const float4* src = (const float4*)(g_wblob + h * BLOBSZ);
            float4* dst = (float4*)(smem + OFF_BW);
            for (int k = tid; k < BLOBSZ / 16; k += 256) dst[k] = src[k];
            if (tid < 64) {
                float av = avec[h * 64 + tid];
                aS[tid] = av; a8[tid] = 0.8f * av;
            }
        }
        __syncthreads();

        // ---- projection: shared-B passes (Whi x {ahi,alo}) then (Wlo x ahi) ----
        {
            uint32_t ahi[4][4], alo[4][4];
            uint32_t abase = sb + OFF_AX + (ib + (lid & 15)) * XLD + ((lid >> 4) << 4);
            #pragma unroll
            for (int kc = 0; kc < 4; kc++) {
                ldsm4(ahi[kc], abase + kc * 32);
                ldsm4(alo[kc], abase + 64 * XLD + kc * 32);
            }
            float pacc[8][4];
            #pragma unroll
            for (int t = 0; t < 8; t++) { pacc[t][0] = pacc[t][1] = pacc[t][2] = pacc[t][3] = 0.f; }
            #pragma unroll
            for (int kc = 0; kc < 4; kc++) {   // Whi: 2 hmma per fragment
                uint32_t wb = sb + OFF_BW + ((kc << 4) + (lid & 15)) * WLD
                            + nh * 128 + ((lid >> 4) << 4);
                #pragma unroll
                for (int np = 0; np < 4; np++) {
                    uint32_t bf[4];
                    ldsm4t(bf, wb + np * 32);
                    hmma(pacc[2 * np],     ahi[kc], bf[0], bf[1]);
                    hmma(pacc[2 * np + 1], ahi[kc], bf[2], bf[3]);
                    hmma(pacc[2 * np],     alo[kc], bf[0], bf[1]);
                    hmma(pacc[2 * np + 1], alo[kc], bf[2], bf[3]);
                }
            }
            #pragma unroll
            for (int kc = 0; kc < 4; kc++) {   // Wlo: ahi only
                uint32_t wb = sb + OFF_BW + 17408 + ((kc << 4) + (lid & 15)) * WLD
                            + nh * 128 + ((lid >> 4) << 4);
                #pragma unroll
                for (int np = 0; np < 4; np++) {
                    uint32_t bf[4];
                    ldsm4t(bf, wb + np * 32);
                    hmma(pacc[2 * np],     ahi[kc], bf[0], bf[1]);
                    hmma(pacc[2 * np + 1], ahi[kc], bf[2], bf[3]);
                }
            }
            float va = 0.f, vb = 0.f;
            if (nh == 0) {      // S rows: fp32 + bf16-split + p-dot
                #pragma unroll
                for (int nt = 0; nt < 8; nt++) {
                    int u = (nt << 3) + nc;
                    float2 av = *(const float2*)&aS[u];
                    va += av.x * pacc[nt][0] + av.y * pacc[nt][1];
                    vb += av.x * pacc[nt][2] + av.y * pacc[nt][3];
                    *(float2*)&Sf[(ib + mr) * LDs + u]     = make_float2(pacc[nt][0], pacc[nt][1]);
                    *(float2*)&Sf[(ib + mr + 8) * LDs + u] = make_float2(pacc[nt][2], pacc[nt][3]);
                    uint32_t hw, lw;
                    split2(pacc[nt][0], pacc[nt][1], hw, lw);
                    *(uint32_t*)(smem + OFF_SBF + (ib + mr) * WLD + (u << 1))       = hw;
                    *(uint32_t*)(smem + OFF_SBF + (ib + mr) * WLD + 128 + (u << 1)) = lw;
                    split2(pacc[nt][2], pacc[nt][3], hw, lw);
                    *(uint32_t*)(smem + OFF_SBF + (ib + mr + 8) * WLD + (u << 1))       = hw;
                    *(uint32_t*)(smem + OFF_SBF + (ib + mr + 8) * WLD + 128 + (u << 1)) = lw;
                }
            } else {            // D rows -> transposed Dt + q-dot
                #pragma unroll
                for (int nt = 0; nt < 8; nt++) {
                    int u = (nt << 3) + nc;
                    float2 av = *(const float2*)&aS[u];
                    va += av.x * pacc[nt][0] + av.y * pacc[nt][1];
                    vb += av.x * pacc[nt][2] + av.y * pacc[nt][3];
                    Dt[u * LDs + ib + mr]           = pacc[nt][0];
                    Dt[(u + 1) * LDs + ib + mr]     = pacc[nt][1];
                    Dt[u * LDs + ib + mr + 8]       = pacc[nt][2];
                    Dt[(u + 1) * LDs + ib + mr + 8] = pacc[nt][3];
                }
            }
            va += __shfl_xor_sync(~0u, va, 1); va += __shfl_xor_sync(~0u, va, 2);
            vb += __shfl_xor_sync(~0u, vb, 1); vb += __shfl_xor_sync(~0u, vb, 2);
            if ((lid & 3) == 0) {
                if (nh == 0) { ps[ib + mr] = va; ps[ib + mr + 8] = vb; }
                else         { qs[ib + mr] = va; qs[ib + mr + 8] = vb; }
            }
        }
        __syncthreads();

        // ---- pairwise + masked softmax fused (4x4 tile; 16-lane row shfl) ----
        {
            unsigned long long acc0[4], acc1[4];
            #pragma unroll
            for (int ii = 0; ii < 4; ii++) { acc0[ii] = 0ull; acc1[ii] = 0ull; }
            #pragma unroll 2
            for (int u4 = 0; u4 < 64; u4 += 4) {
                float4 a84 = *(const float4*)&a8[u4];
                float4 s0 = *(const float4*)&Sf[(r0 + 0) * LDs + u4];
                float4 s1 = *(const float4*)&Sf[(r0 + 1) * LDs + u4];
                float4 s2 = *(const float4*)&Sf[(r0 + 2) * LDs + u4];
                float4 s3 = *(const float4*)&Sf[(r0 + 3) * LDs + u4];
                #pragma unroll
                for (int uu = 0; uu < 4; uu++) {
                    ulonglong2 d2 = *(const ulonglong2*)&Dt[(u4 + uu) * LDs + c0];
                    float a8u = f4get(a84, uu);
                    unsigned long long a2 = pack2(a8u, a8u);
#define PR(K, SR) { float s_ = f4get(SR, uu); unsigned long long s2_ = pack2(s_, s_); \
                    acc0[K] = fma2(a2, relu2(add2(s2_, d2.x)), acc0[K]);              \
                    acc1[K] = fma2(a2, relu2(add2(s2_, d2.y)), acc1[K]); }
                    PR(0, s0) PR(1, s1) PR(2, s2) PR(3, s3)
#undef PR
                }
            }
            float q0 = qs[c0], q1 = qs[c0 + 1], q2 = qs[c0 + 2], q3 = qs[c0 + 3];
            float v[4][4], mx[4];
            #pragma unroll
            for (int ii = 0; ii < 4; ii++) {
                float pi = ps[r0 + ii];
                unpack2(acc0[ii], v[ii][0], v[ii][1]);
                unpack2(acc1[ii], v[ii][2], v[ii][3]);
                unsigned mrow = (unsigned)(adjb[r0 + ii] >> c0) & 0xFu;
                v[ii][0] = (mrow & 1u) ? (0.2f * (pi + q0) + v[ii][0]) : -1e9f;
                v[ii][1] = (mrow & 2u) ? (0.2f * (pi + q1) + v[ii][1]) : -1e9f;
                v[ii][2] = (mrow & 4u) ? (0.2f * (pi + q2) + v[ii][2]) : -1e9f;
                v[ii][3] = (mrow & 8u) ? (0.2f * (pi + q3) + v[ii][3]) : -1e9f;
                mx[ii] = fmaxf(fmaxf(v[ii][0], v[ii][1]), fmaxf(v[ii][2], v[ii][3]));
            }
            #pragma unroll
            for (int s = 1; s <= 8; s <<= 1) {
                #pragma unroll
                for (int ii = 0; ii < 4; ii++)
                    mx[ii] = fmaxf(mx[ii], __shfl_xor_sync(~0u, mx[ii], s));
            }
            float sm[4];
            #pragma unroll
            for (int ii = 0; ii < 4; ii++) {
                float e0 = exp2f((v[ii][0] - mx[ii]) * 1.4426950408889634f);
                float e1 = exp2f((v[ii][1] - mx[ii]) * 1.4426950408889634f);
                float e2 = exp2f((v[ii][2] - mx[ii]) * 1.4426950408889634f);
                float e3 = exp2f((v[ii][3] - mx[ii]) * 1.4426950408889634f);
                v[ii][0] = e0; v[ii][1] = e1; v[ii][2] = e2; v[ii][3] = e3;
                sm[ii] = (e0 + e1) + (e2 + e3);
            }
            #pragma unroll
            for (int s = 1; s <= 8; s <<= 1) {
                #pragma unroll
                for (int ii = 0; ii < 4; ii++)
                    sm[ii] += __shfl_xor_sync(~0u, sm[ii], s);
            }
            #pragma unroll
            for (int ii = 0; ii < 4; ii++) {
                float inv = 1.0f / sm[ii];
                uint32_t hw0, lw0, hw1, lw1;
                split2(v[ii][0] * inv, v[ii][1] * inv, hw0, lw0);
                split2(v[ii][2] * inv, v[ii][3] * inv, hw1, lw1);
                unsigned char* ab = (unsigned char*)smem + OFF_ATT + (r0 + ii) * WLD + (c0 << 1);
                *(uint2*)ab         = make_uint2(hw0, hw1);
                *(uint2*)(ab + 128) = make_uint2(lw0, lw1);
            }
        }
        __syncthreads();

        // ---- aggregation: shared-B passes (S_hi x {athi,atlo}) then (S_lo x athi) ----
        {
            uint32_t athi[4][4], atlo[4][4];
            uint32_t tb = sb + OFF_ATT + (ib + (lid & 15)) * WLD + ((lid >> 4) << 4);
            #pragma unroll
            for (int kc = 0; kc < 4; kc++) {
                ldsm4(athi[kc], tb + kc * 32);
                ldsm4(atlo[kc], tb + 128 + kc * 32);
            }
            #pragma unroll
            for (int kc = 0; kc < 4; kc++) {   // S_hi: 2 hmma per fragment
                uint32_t sbB = sb + OFF_SBF + ((kc << 4) + (lid & 15)) * WLD
                             + nh * 64 + ((lid >> 4) << 4);
                #pragma unroll
                for (int np = 0; np < 2; np++) {
                    uint32_t bf[4];
                    ldsm4t(bf, sbB + np * 32);
                    hmma(cacc[2 * np],     athi[kc], bf[0], bf[1]);
                    hmma(cacc[2 * np + 1], athi[kc], bf[2], bf[3]);
                    hmma(cacc[2 * np],     atlo[kc], bf[0], bf[1]);
                    hmma(cacc[2 * np + 1], atlo[kc], bf[2], bf[3]);
                }
            }
            #pragma unroll
            for (int kc = 0; kc < 4; kc++) {   // S_lo: athi only
                uint32_t sbB = sb + OFF_SBF + ((kc << 4) + (lid & 15)) * WLD
                             + 128 + nh * 64 + ((lid >> 4) << 4);
                #pragma unroll
                for (int np = 0; np < 2; np++) {
                    uint32_t bf[4];
                    ldsm4t(bf, sbB + np * 32);
                    hmma(cacc[2 * np],     athi[kc], bf[0], bf[1]);
                    hmma(cacc[2 * np + 1], athi[kc], bf[2], bf[3]);
                }
            }
        }
        __syncthreads();
    }

    // ---- write mean over heads ----
    float* op = outp + bt * 4096;
    #pragma unroll
    for (int nt = 0; nt < 4; nt++) {
        int u = (nh << 5) + (nt << 3) + nc;
        *(float2*)&op[(ib + mr) * 64 + u]     = make_float2(0.25f * cacc[nt][0], 0.25f * cacc[nt][1]);
        *(float2*)&op[(ib + mr + 8) * 64 + u] = make_float2(0.25f * cacc[nt][2], 0.25f * cacc[nt][3]);
    }
}

extern "C" void kernel_launch(void* const* d_in, const int* in_sizes, int n_in,
                              void* d_out, int out_size) {
    const float* feat = (const float*)d_in[0];
    const int*   adj  = (const int*)d_in[1];
    const float* Wsrc = (const float*)d_in[2];
    const float* Wdst = (const float*)d_in[3];
    const float* avec = (const float*)d_in[4];

    cudaFuncSetAttribute((const void*)gat_mma_kernel,
                         cudaFuncAttributeMaxDynamicSharedMemorySize, SMEM_TOTAL);
    prep_w<<<4, 256>>>(Wsrc, Wdst);
    gat_mma_kernel<<<256, 256, SMEM_TOTAL>>>(feat, adj, avec, (float*)d_out);
}

// round 17
// speedup vs baseline: 1.3474x; 1.0135x over previous
#include <cuda_runtime.h>
#include <cuda_bf16.h>
#include <cstdint>

// GATv2 fused: B=8,T=32,N=64,F=64,U=64,H=4 (BT=256), one CTA/graph.
// Proj + agg on mma.sync.m16n8k16.bf16 (3-term split, fp32 acc), B-fragment
// shared across hi/lo A passes. p/q + S-split fused into proj epilogue.
// Pairwise uses |x| identity: score = 0.6(p+q) + sum 0.4a|s+d| (FFMA+|mod|),
// fused with masked softmax in registers (4x4 tile, 16-lane shfl).

#define XLD 144
#define WLD 272
#define LDs 68
#define OFF_AX 0
#define OFF_BW 18432
#define OFF_ATT 18432            // overlay on Whi region (softmax-written)
#define OFF_SF 53248
#define OFF_DT 70656
#define OFF_SBF 88064            // dedicated: written during proj epilogue
#define OFF_AS 105472
#define OFF_A4 105728
#define OFF_PS 105984
#define OFF_QS 106240
#define OFF_ADJ 106496
#define SMEM_TOTAL 107008
#define BLOBSZ 34816

__device__ __align__(256) unsigned char g_wblob[4 * BLOBSZ];

__device__ __forceinline__ uint32_t smem_u32(const void* p) {
    uint32_t a;
    asm("{ .reg .u64 t; cvta.to.shared.u64 t, %1; cvt.u32.u64 %0, t; }" : "=r"(a) : "l"(p));
    return a;
}
__device__ __forceinline__ void ldsm4(uint32_t* r, uint32_t a) {
    asm volatile("ldmatrix.sync.aligned.m8n8.x4.shared.b16 {%0,%1,%2,%3}, [%4];"
        : "=r"(r[0]), "=r"(r[1]), "=r"(r[2]), "=r"(r[3]) : "r"(a));
}
__device__ __forceinline__ void ldsm4t(uint32_t* r, uint32_t a) {
    asm volatile("ldmatrix.sync.aligned.m8n8.x4.trans.shared.b16 {%0,%1,%2,%3}, [%4];"
        : "=r"(r[0]), "=r"(r[1]), "=r"(r[2]), "=r"(r[3]) : "r"(a));
}
__device__ __forceinline__ void hmma(float* c, const uint32_t* a, uint32_t b0, uint32_t b1) {
    asm volatile("mma.sync.aligned.m16n8k16.row.col.f32.bf16.bf16.f32 "
        "{%0,%1,%2,%3}, {%4,%5,%6,%7}, {%8,%9}, {%0,%1,%2,%3};"
        : "+f"(c[0]), "+f"(c[1]), "+f"(c[2]), "+f"(c[3])
        : "r"(a[0]), "r"(a[1]), "r"(a[2]), "r"(a[3]), "r"(b0), "r"(b1));
}
__device__ __forceinline__ float f4get(const float4& v, int i) {
    switch (i & 3) { case 0: return v.x; case 1: return v.y; case 2: return v.z; default: return v.w; }
}
__device__ __forceinline__ void split2(float v0, float v1, uint32_t& hw, uint32_t& lw) {
    asm("cvt.rn.bf16x2.f32 %0, %2, %1;" : "=r"(hw) : "f"(v0), "f"(v1));
    float h0 = __uint_as_float(hw << 16);
    float h1 = __uint_as_float(hw & 0xFFFF0000u);
    float r0 = v0 - h0, r1 = v1 - h1;
    asm("cvt.rn.bf16x2.f32 %0, %2, %1;" : "=r"(lw) : "f"(r0), "f"(r1));
}

__global__ void prep_w(const float* __restrict__ Ws, const float* __restrict__ Wd) {
    int h = blockIdx.x;
    unsigned char* base = g_wblob + h * BLOBSZ;
    for (int idx = threadIdx.x; idx < 64 * 128; idx += 256) {
        int k = idx >> 7, n = idx & 127;
        float w = (n < 64) ? Ws[h * 4096 + k * 64 + n] : Wd[h * 4096 + k * 64 + (n - 64)];
        __nv_bfloat16 hi = __float2bfloat16(w);
        __nv_bfloat16 lo = __float2bfloat16(w - __bfloat162float(hi));
        int byt = (k * 136 + n) * 2;
        *(unsigned short*)(base + byt)         = __bfloat16_as_ushort(hi);
        *(unsigned short*)(base + 17408 + byt) = __bfloat16_as_ushort(lo);
    }
}

__global__ void __launch_bounds__(256, 2) gat_mma_kernel(
    const float* __restrict__ feat, const int* __restrict__ adj,
    const float* __restrict__ avec, float* __restrict__ outp)
{
    extern __shared__ char smem[];
    const uint32_t sb = smem_u32(smem);   // shared-space: ONLY for ldmatrix/mma asm
    float* Sf = (float*)(smem + OFF_SF);
    float* Dt = (float*)(smem + OFF_DT);
    float* aS = (float*)(smem + OFF_AS);
    float* a4 = (float*)(smem + OFF_A4);
    float* ps = (float*)(smem + OFF_PS);
    float* qs = (float*)(smem + OFF_QS);
    unsigned long long* adjb = (unsigned long long*)(smem + OFF_ADJ);

    const int tid = threadIdx.x, wid = tid >> 5, lid = tid & 31;
    const int bt = blockIdx.x, b = bt >> 5;
    const int ty = tid >> 4, tx = tid & 15;
    const int r0 = ty << 2, c0 = tx << 2;
    const int mr = lid >> 2, nc = (lid & 3) << 1;
    const int ib = (wid & 3) << 4;
    const int nh = wid >> 2;

    // ---- stage X split + adjacency ----
    {
        const float4* xp = (const float4*)(feat + bt * 4096);
        for (int idx = tid; idx < 1024; idx += 256) {
            float4 v = xp[idx];
            int i = idx >> 4, f0 = (idx & 15) << 2;
            uint32_t h01, l01, h23, l23;
            split2(v.x, v.y, h01, l01);
            split2(v.z, v.w, h23, l23);
            *(uint2*)(smem + OFF_AX + i * XLD + f0 * 2)        = make_uint2(h01, h23);
            *(uint2*)(smem + OFF_AX + (64 + i) * XLD + f0 * 2) = make_uint2(l01, l23);
        }
        if (tid < 64) {
            const int* ar = adj + b * 4096 + tid * 64;
            unsigned long long m = 1ull << tid;
            #pragma unroll 8
            for (int j = 0; j < 64; j++) if (ar[j] > 0) m |= (1ull << j);
            adjb[tid] = m;
        }
    }

    float cacc[4][4];
    #pragma unroll
    for (int t = 0; t < 4; t++) { cacc[t][0] = cacc[t][1] = cacc[t][2] = cacc[t][3] = 0.f; }

    for (int h = 0; h < 4; h++) {
        {   // ---- stage W blob + a ----
            const float4* src = (const float4*)(g_wblob + h * BLOBSZ);
            float4* dst = (float4*)(smem + OFF_BW);
            for (int k = tid; k < BLOBSZ / 16; k += 256) dst[k] = src[k];
            if (tid < 64) {
                float av = avec[h * 64 + tid];
                aS[tid] = av; a4[tid] = 0.4f * av;
            }
        }
        __syncthreads();

        // ---- projection: shared-B passes (Whi x {ahi,alo}) then (Wlo x ahi) ----
        {
            uint32_t ahi[4][4], alo[4][4];
            uint32_t abase = sb + OFF_AX + (ib + (lid & 15)) * XLD + ((lid >> 4) << 4);
            #pragma unroll
            for (int kc = 0; kc < 4; kc++) {
                ldsm4(ahi[kc], abase + kc * 32);
                ldsm4(alo[kc], abase + 64 * XLD + kc * 32);
            }
            float pacc[8][4];
            #pragma unroll
            for (int t = 0; t < 8; t++) { pacc[t][0] = pacc[t][1] = pacc[t][2] = pacc[t][3] = 0.f; }
            #pragma unroll
            for (int kc = 0; kc < 4; kc++) {   // Whi: 2 hmma per fragment
                uint32_t wb = sb + OFF_BW + ((kc << 4) + (lid & 15)) * WLD
                            + nh * 128 + ((lid >> 4) << 4);
                #pragma unroll
                for (int np = 0; np < 4; np++) {
                    uint32_t bf[4];
                    ldsm4t(bf, wb + np * 32);
                    hmma(pacc[2 * np],     ahi[kc], bf[0], bf[1]);
                    hmma(pacc[2 * np + 1], ahi[kc], bf[2], bf[3]);
                    hmma(pacc[2 * np],     alo[kc], bf[0], bf[1]);
                    hmma(pacc[2 * np + 1], alo[kc], bf[2], bf[3]);
                }
            }
            #pragma unroll
            for (int kc = 0; kc < 4; kc++) {   // Wlo: ahi only
                uint32_t wb = sb + OFF_BW + 17408 + ((kc << 4) + (lid & 15)) * WLD
                            + nh * 128 + ((lid >> 4) << 4);
                #pragma unroll
                for (int np = 0; np < 4; np++) {
                    uint32_t bf[4];
                    ldsm4t(bf, wb + np * 32);
                    hmma(pacc[2 * np],     ahi[kc], bf[0], bf[1]);
                    hmma(pacc[2 * np + 1], ahi[kc], bf[2], bf[3]);
                }
            }
            float va = 0.f, vb = 0.f;
            if (nh == 0) {      // S rows: fp32 + bf16-split + p-dot
                #pragma unroll
                for (int nt = 0; nt < 8; nt++) {
                    int u = (nt << 3) + nc;
                    float2 av = *(const float2*)&aS[u];
                    va += av.x * pacc[nt][0] + av.y * pacc[nt][1];
                    vb += av.x * pacc[nt][2] + av.y * pacc[nt][3];
                    *(float2*)&Sf[(ib + mr) * LDs + u]     = make_float2(pacc[nt][0], pacc[nt][1]);
                    *(float2*)&Sf[(ib + mr + 8) * LDs + u] = make_float2(pacc[nt][2], pacc[nt][3]);
                    uint32_t hw, lw;
                    split2(pacc[nt][0], pacc[nt][1], hw, lw);
                    *(uint32_t*)(smem + OFF_SBF + (ib + mr) * WLD + (u << 1))       = hw;
                    *(uint32_t*)(smem + OFF_SBF + (ib + mr) * WLD + 128 + (u << 1)) = lw;
                    split2(pacc[nt][2], pacc[nt][3], hw, lw);
                    *(uint32_t*)(smem + OFF_SBF + (ib + mr + 8) * WLD + (u << 1))       = hw;
                    *(uint32_t*)(smem + OFF_SBF + (ib + mr + 8) * WLD + 128 + (u << 1)) = lw;
                }
            } else {            // D rows -> transposed Dt + q-dot
                #pragma unroll
                for (int nt = 0; nt < 8; nt++) {
                    int u = (nt << 3) + nc;
                    float2 av = *(const float2*)&aS[u];
                    va += av.x * pacc[nt][0] + av.y * pacc[nt][1];
                    vb += av.x * pacc[nt][2] + av.y * pacc[nt][3];
                    Dt[u * LDs + ib + mr]           = pacc[nt][0];
                    Dt[(u + 1) * LDs + ib + mr]     = pacc[nt][1];
                    Dt[u * LDs + ib + mr + 8]       = pacc[nt][2];
                    Dt[(u + 1) * LDs + ib + mr + 8] = pacc[nt][3];
                }
            }
            va += __shfl_xor_sync(~0u, va, 1); va += __shfl_xor_sync(~0u, va, 2);
            vb += __shfl_xor_sync(~0u, vb, 1); vb += __shfl_xor_sync(~0u, vb, 2);
            if ((lid & 3) == 0) {
                if (nh == 0) { ps[ib + mr] = va; ps[ib + mr + 8] = vb; }
                else         { qs[ib + mr] = va; qs[ib + mr + 8] = vb; }
            }
        }
        __syncthreads();

        // ---- pairwise (|x| identity, scalar FFMA) + masked softmax fused ----
        {
            float acc[4][4];
            #pragma unroll
            for (int ii = 0; ii < 4; ii++)
                acc[ii][0] = acc[ii][1] = acc[ii][2] = acc[ii][3] = 0.f;
            #pragma unroll 2
            for (int u4 = 0; u4 < 64; u4 += 4) {
                float4 a44 = *(const float4*)&a4[u4];
                float4 s0 = *(const float4*)&Sf[(r0 + 0) * LDs + u4];
                float4 s1 = *(const float4*)&Sf[(r0 + 1) * LDs + u4];
                float4 s2 = *(const float4*)&Sf[(r0 + 2) * LDs + u4];
                float4 s3 = *(const float4*)&Sf[(r0 + 3) * LDs + u4];
                #pragma unroll
                for (int uu = 0; uu < 4; uu++) {
                    float4 dv = *(const float4*)&Dt[(u4 + uu) * LDs + c0];
                    float au = f4get(a44, uu);
#define PRS(K, SR) { float s_ = f4get(SR, uu);                                    \
                    acc[K][0] = fmaf(au, fabsf(s_ + dv.x), acc[K][0]);            \
                    acc[K][1] = fmaf(au, fabsf(s_ + dv.y), acc[K][1]);            \
                    acc[K][2] = fmaf(au, fabsf(s_ + dv.z), acc[K][2]);            \
                    acc[K][3] = fmaf(au, fabsf(s_ + dv.w), acc[K][3]); }
                    PRS(0, s0) PRS(1, s1) PRS(2, s2) PRS(3, s3)
#undef PRS
                }
            }
            float q0 = qs[c0], q1 = qs[c0 + 1], q2 = qs[c0 + 2], q3 = qs[c0 + 3];
            float v[4][4], mx[4];
            #pragma unroll
            for (int ii = 0; ii < 4; ii++) {
                float pi = ps[r0 + ii];
                unsigned mrow = (unsigned)(adjb[r0 + ii] >> c0) & 0xFu;
                v[ii][0] = (mrow & 1u) ? (0.6f * (pi + q0) + acc[ii][0]) : -1e9f;
                v[ii][1] = (mrow & 2u) ? (0.6f * (pi + q1) + acc[ii][1]) : -1e9f;
                v[ii][2] = (mrow & 4u) ? (0.6f * (pi + q2) + acc[ii][2]) : -1e9f;
                v[ii][3] = (mrow & 8u) ? (0.6f * (pi + q3) + acc[ii][3]) : -1e9f;
                mx[ii] = fmaxf(fmaxf(v[ii][0], v[ii][1]), fmaxf(v[ii][2], v[ii][3]));
            }
            #pragma unroll
            for (int s = 1; s <= 8; s <<= 1) {
                #pragma unroll
                for (int ii = 0; ii < 4; ii++)
                    mx[ii] = fmaxf(mx[ii], __shfl_xor_sync(~0u, mx[ii], s));
            }
            float sm[4];
            #pragma unroll
            for (int ii = 0; ii < 4; ii++) {
                float e0 = exp2f((v[ii][0] - mx[ii]) * 1.4426950408889634f);
                float e1 = exp2f((v[ii][1] - mx[ii]) * 1.4426950408889634f);
                float e2 = exp2f((v[ii][2] - mx[ii]) * 1.4426950408889634f);
                float e3 = exp2f((v[ii][3] - mx[ii]) * 1.4426950408889634f);
                v[ii][0] = e0; v[ii][1] = e1; v[ii][2] = e2; v[ii][3] = e3;
                sm[ii] = (e0 + e1) + (e2 + e3);
            }
            #pragma unroll
            for (int s = 1; s <= 8; s <<= 1) {
                #pragma unroll
                for (int ii = 0; ii < 4; ii++)
                    sm[ii] += __shfl_xor_sync(~0u, sm[ii], s);
            }
            #pragma unroll
            for (int ii = 0; ii < 4; ii++) {
                float inv = 1.0f / sm[ii];
                uint32_t hw0, lw0, hw1, lw1;
                split2(v[ii][0] * inv, v[ii][1] * inv, hw0, lw0);
                split2(v[ii][2] * inv, v[ii][3] * inv, hw1, lw1);
                unsigned char* ab = (unsigned char*)smem + OFF_ATT + (r0 + ii) * WLD + (c0 << 1);
                *(uint2*)ab         = make_uint2(hw0, hw1);
                *(uint2*)(ab + 128) = make_uint2(lw0, lw1);
            }
        }
        __syncthreads();

        // ---- aggregation: shared-B passes (S_hi x {athi,atlo}) then (S_lo x athi) ----
        {
            uint32_t athi[4][4], atlo[4][4];
            uint32_t tb = sb + OFF_ATT + (ib + (lid & 15)) * WLD + ((lid >> 4) << 4);
            #pragma unroll
            for (int kc = 0; kc < 4; kc++) {
                ldsm4(athi[kc], tb + kc * 32);
                ldsm4(atlo[kc], tb + 128 + kc * 32);
            }
            #pragma unroll
            for (int kc = 0; kc < 4; kc++) {   // S_hi: 2 hmma per fragment
                uint32_t sbB = sb + OFF_SBF + ((kc << 4) + (lid & 15)) * WLD
                             + nh * 64 + ((lid >> 4) << 4);
                #pragma unroll
                for (int np = 0; np < 2; np++) {
                    uint32_t bf[4];
                    ldsm4t(bf, sbB + np * 32);
                    hmma(cacc[2 * np],     athi[kc], bf[0], bf[1]);
                    hmma(cacc[2 * np + 1], athi[kc], bf[2], bf[3]);
                    hmma(cacc[2 * np],     atlo[kc], bf[0], bf[1]);
                    hmma(cacc[2 * np + 1], atlo[kc], bf[2], bf[3]);
                }
            }
            #pragma unroll
            for (int kc = 0; kc < 4; kc++) {   // S_lo: athi only
                uint32_t sbB = sb + OFF_SBF + ((kc << 4) + (lid & 15)) * WLD
                             + 128 + nh * 64 + ((lid >> 4) << 4);
                #pragma unroll
                for (int np = 0; np < 2; np++) {
                    uint32_t bf[4];
                    ldsm4t(bf, sbB + np * 32);
                    hmma(cacc[2 * np],     athi[kc], bf[0], bf[1]);
                    hmma(cacc[2 * np + 1], athi[kc], bf[2], bf[3]);
                }
            }
        }
        __syncthreads();
    }

    // ---- write mean over heads ----
    float* op = outp + bt * 4096;
    #pragma unroll
    for (int nt = 0; nt < 4; nt++) {
        int u = (nh << 5) + (nt << 3) + nc;
        *(float2*)&op[(ib + mr) * 64 + u]     = make_float2(0.25f * cacc[nt][0], 0.25f * cacc[nt][1]);
        *(float2*)&op[(ib + mr + 8) * 64 + u] = make_float2(0.25f * cacc[nt][2], 0.25f * cacc[nt][3]);
    }
}

extern "C" void kernel_launch(void* const* d_in, const int* in_sizes, int n_in,
                              void* d_out, int out_size) {
    const float* feat = (const float*)d_in[0];
    const int*   adj  = (const int*)d_in[1];
    const float* Wsrc = (const float*)d_in[2];
    const float* Wdst = (const float*)d_in[3];
    const float* avec = (const float*)d_in[4];

    cudaFuncSetAttribute((const void*)gat_mma_kernel,
                         cudaFuncAttributeMaxDynamicSharedMemorySize, SMEM_TOTAL);
    prep_w<<<4, 256>>>(Wsrc, Wdst);
    gat_mma_kernel<<<256, 256, SMEM_TOTAL>>>(feat, adj, avec, (float*)d_out);
}